// round 8
// baseline (speedup 1.0000x reference)
#include <cuda_runtime.h>
#include <cstdint>

#define TT     224
#define HH     128
#define BB     64
#define SS     20
#define NN     1280      // BB*SS
#define G4     4         // sequences per LSTM CTA
#define NG     320       // NN/G4
#define NINTER 64
#define KSPLIT 8
#define TM     32        // seq tile in feats GEMM
#define TCHUNK 28        // 224/KSPLIT timesteps per k-split

typedef unsigned long long u64;

// ---------------- scratch (static device globals; no runtime allocation) ---------
__device__ __align__(16) float g_hs[(size_t)NN * TT * HH];   // [n][t][h]
__device__ int   g_len[NN];
__device__ int   g_order[NN];
__device__ int   g_hist[256];
__device__ int   g_off[256];
__device__ __align__(16) float g_Wk[512 * 128];              // [p2][r] float4: W[r][4p2..4p2+3]
__device__ __align__(16) float g_psum[(size_t)KSPLIT * NN * NINTER];

// ---------------- helpers ----------------
__device__ __forceinline__ u64 ffma2(u64 a, u64 b, u64 c) {
    u64 d;
    asm("fma.rn.f32x2 %0, %1, %2, %3;" : "=l"(d) : "l"(a), "l"(b), "l"(c));
    return d;
}
__device__ __forceinline__ float f2lo(u64 v) { return __uint_as_float((unsigned)(v & 0xffffffffull)); }
__device__ __forceinline__ float f2hi(u64 v) { return __uint_as_float((unsigned)(v >> 32)); }
__device__ __forceinline__ float sigf(float v) {
    return __fdividef(1.0f, 1.0f + __expf(-v));
}
__device__ __forceinline__ float tanh_(float v) {
    float e = __expf(-2.0f * v);
    return __fdividef(1.0f - e, 1.0f + e);
}

// ---------------- kernel 0: zero histogram ---------------------------------------
__global__ void k_zero_hist() {
    if (threadIdx.x < 256) g_hist[threadIdx.x] = 0;
}

// ---------------- kernel 1: ragged lengths + histogram ---------------------------
__global__ void k_lens(const float* __restrict__ x) {
    int n = blockIdx.x;
    const float* xs = x + (size_t)n * TT;
    int first = 1 << 30;
    for (int t = threadIdx.x; t < TT; t += 32)
        if (xs[t] == 0.0f) first = min(first, t);
    #pragma unroll
    for (int o = 16; o; o >>= 1)
        first = min(first, __shfl_xor_sync(0xffffffffu, first, o));
    if (threadIdx.x == 0) {
        int len = (first == 0 || first >= TT) ? TT : (first + 1);
        g_len[n] = len;
        atomicAdd(&g_hist[len], 1);
    }
}

// ---------------- kernel 2: prefix sum over hist ---------------------------------
__global__ void k_prefix() {
    if (threadIdx.x == 0) {
        int acc = 0;
        for (int i = 0; i < 256; i++) { g_off[i] = acc; acc += g_hist[i]; }
    }
}

// ---------------- kernel 3: counting-sort scatter (ascending by len) -------------
__global__ void k_scatter() {
    int n = blockIdx.x * blockDim.x + threadIdx.x;
    if (n < NN) {
        int pos = atomicAdd(&g_off[g_len[n]], 1);
        g_order[pos] = n;
    }
}

// ---------------- kernel 4: repack W_hh: g_Wk[p2*512 + r] = W[r][4p2..4p2+3] -----
__global__ void k_wt(const float* __restrict__ Whh) {
    int j = blockIdx.x * blockDim.x + threadIdx.x;   // 0..16383
    int r  = j & 511;
    int p2 = j >> 9;
    float4 v = ((const float4*)Whh)[r * 32 + p2];
    ((float4*)g_Wk)[p2 * 512 + r] = v;
}

// ---------------- kernel 5: LSTM ------------------------------------------------
// 256 threads. po = tid&1, u = tid>>1.
//   even lane (po=0): rows u (gate i), 128+u (gate f);   owns cells of seqs 0,1
//   odd  lane (po=1): rows 256+u (gate g), 384+u (gate o); owns cells of seqs 2,3
// Gate exchange between lane pairs via shfl.bfly(1). ONE barrier per timestep.
// dynamic smem:
//   [0, 131072)        sW  : float4[16*512]   weight k-quads p2=0..15
//   [131072, 135168)   shf : float[2][4][128] double-buffered h
//   [135168, 138752)   sx  : float[4][224]
#define LSTM_SMEM 138752
__global__ void __launch_bounds__(256, 1) k_lstm(
    const float* __restrict__ x, const float* __restrict__ Wih,
    const float* __restrict__ bih, const float* __restrict__ bhh)
{
    extern __shared__ __align__(16) char dyn[];
    ulonglong2* sW = (ulonglong2*)dyn;
    float* shf = (float*)(dyn + 131072);
    float* sx  = (float*)(dyn + 135168);
    __shared__ int sn[G4], sl[G4];

    int tid = threadIdx.x;
    int po = tid & 1;
    int u  = tid >> 1;
    int r0 = po * 256 + u;       // gate 2*po
    int r1 = r0 + 128;           // gate 2*po+1

    int g = (NG - 1) - blockIdx.x;   // longest groups first
    if (tid < G4) {
        int n = g_order[g * G4 + tid];
        sn[tid] = n;
        sl[tid] = g_len[n];
    }

    // stage smem weight half (p2 = 0..15)
    const float4* Wk4 = (const float4*)g_Wk;
    float4* sW4 = (float4*)sW;
    for (int i = tid; i < 16 * 512; i += 256) sW4[i] = Wk4[i];
    // zero both h buffers
    for (int i = tid; i < 1024; i += 256) shf[i] = 0.0f;

    // register weight half (p2 = 16..31) for this thread's two rows
    ulonglong2 wr0[16], wr1[16];
    const ulonglong2* Wk2 = (const ulonglong2*)g_Wk;
    #pragma unroll
    for (int i = 0; i < 16; i++) {
        wr0[i] = Wk2[(size_t)(16 + i) * 512 + r0];
        wr1[i] = Wk2[(size_t)(16 + i) * 512 + r1];
    }

    float wi0 = Wih[r0], bs0 = bih[r0] + bhh[r0];
    float wi1 = Wih[r1], bs1 = bih[r1] + bhh[r1];

    __syncthreads();
    int l0 = sl[0], l1 = sl[1], l2 = sl[2], l3 = sl[3];
    int maxlen = max(max(l0, l1), max(l2, l3));

    #pragma unroll
    for (int m = 0; m < G4; m++)
        for (int t = tid; t < TT; t += 256) sx[m * TT + t] = x[(size_t)sn[m] * TT + t];

    // this thread's two cell slots
    int mA = po * 2, mB = mA + 1;    // even: seqs 0,1 ; odd: seqs 2,3
    int lenA = sl[mA], lenB = sl[mB];
    float* hsA = g_hs + (size_t)sn[mA] * TT * HH + u;
    float* hsB = g_hs + (size_t)sn[mB] * TT * HH + u;
    float cA = 0.0f, cB = 0.0f;
    __syncthreads();

    for (int t = 0; t < maxlen; t++) {
        int cur = t & 1, nxt = cur ^ 1;
        const ulonglong2* hb = (const ulonglong2*)(shf + cur * 512);

        u64 A00 = 0, A01 = 0, A02 = 0, A03 = 0;   // row r0, seqs 0..3
        u64 A10 = 0, A11 = 0, A12 = 0, A13 = 0;   // row r1, seqs 0..3

        #pragma unroll 4
        for (int p2 = 0; p2 < 16; p2++) {
            ulonglong2 w0 = sW[p2 * 512 + r0];
            ulonglong2 w1 = sW[p2 * 512 + r1];
            ulonglong2 h0 = hb[p2], h1 = hb[32 + p2], h2 = hb[64 + p2], h3 = hb[96 + p2];
            A00 = ffma2(w0.x, h0.x, A00); A00 = ffma2(w0.y, h0.y, A00);
            A01 = ffma2(w0.x, h1.x, A01); A01 = ffma2(w0.y, h1.y, A01);
            A02 = ffma2(w0.x, h2.x, A02); A02 = ffma2(w0.y, h2.y, A02);
            A03 = ffma2(w0.x, h3.x, A03); A03 = ffma2(w0.y, h3.y, A03);
            A10 = ffma2(w1.x, h0.x, A10); A10 = ffma2(w1.y, h0.y, A10);
            A11 = ffma2(w1.x, h1.x, A11); A11 = ffma2(w1.y, h1.y, A11);
            A12 = ffma2(w1.x, h2.x, A12); A12 = ffma2(w1.y, h2.y, A12);
            A13 = ffma2(w1.x, h3.x, A13); A13 = ffma2(w1.y, h3.y, A13);
        }
        #pragma unroll
        for (int i = 0; i < 16; i++) {
            int p2 = 16 + i;
            ulonglong2 w0 = wr0[i];
            ulonglong2 w1 = wr1[i];
            ulonglong2 h0 = hb[p2], h1 = hb[32 + p2], h2 = hb[64 + p2], h3 = hb[96 + p2];
            A00 = ffma2(w0.x, h0.x, A00); A00 = ffma2(w0.y, h0.y, A00);
            A01 = ffma2(w0.x, h1.x, A01); A01 = ffma2(w0.y, h1.y, A01);
            A02 = ffma2(w0.x, h2.x, A02); A02 = ffma2(w0.y, h2.y, A02);
            A03 = ffma2(w0.x, h3.x, A03); A03 = ffma2(w0.y, h3.y, A03);
            A10 = ffma2(w1.x, h0.x, A10); A10 = ffma2(w1.y, h0.y, A10);
            A11 = ffma2(w1.x, h1.x, A11); A11 = ffma2(w1.y, h1.y, A11);
            A12 = ffma2(w1.x, h2.x, A12); A12 = ffma2(w1.y, h2.y, A12);
            A13 = ffma2(w1.x, h3.x, A13); A13 = ffma2(w1.y, h3.y, A13);
        }

        float xt0 = sx[t], xt1 = sx[TT + t], xt2 = sx[2 * TT + t], xt3 = sx[3 * TT + t];
        // complete pre-activations for this thread's two gate-rows, 4 seqs
        float P00 = f2lo(A00) + f2hi(A00) + xt0 * wi0 + bs0;
        float P01 = f2lo(A01) + f2hi(A01) + xt1 * wi0 + bs0;
        float P02 = f2lo(A02) + f2hi(A02) + xt2 * wi0 + bs0;
        float P03 = f2lo(A03) + f2hi(A03) + xt3 * wi0 + bs0;
        float P10 = f2lo(A10) + f2hi(A10) + xt0 * wi1 + bs1;
        float P11 = f2lo(A11) + f2hi(A11) + xt1 * wi1 + bs1;
        float P12 = f2lo(A12) + f2hi(A12) + xt2 * wi1 + bs1;
        float P13 = f2lo(A13) + f2hi(A13) + xt3 * wi1 + bs1;

        // lane-pair gate exchange (xor 1):
        //  even provides (i2,i3,f2,f3), receives (g0,g1,o0,o1)
        //  odd  provides (g0,g1,o0,o1), receives (i2,i3,f2,f3)
        float e0 = __shfl_xor_sync(0xffffffffu, po ? P00 : P02, 1);
        float e1 = __shfl_xor_sync(0xffffffffu, po ? P01 : P03, 1);
        float e2 = __shfl_xor_sync(0xffffffffu, po ? P10 : P12, 1);
        float e3 = __shfl_xor_sync(0xffffffffu, po ? P11 : P13, 1);

        // even lane: seqA=0 (i=P00 f=P10 g=e0 o=e2), seqB=1 (i=P01 f=P11 g=e1 o=e3)
        // odd  lane: seqA=2 (i=e0 f=e2 g=P02 o=P12), seqB=3 (i=e1 f=e3 g=P03 o=P13)
        float iA = po ? e0 : P00, fA = po ? e2 : P10, gA = po ? P02 : e0, oA = po ? P12 : e2;
        float iB = po ? e1 : P01, fB = po ? e3 : P11, gB = po ? P03 : e1, oB = po ? P13 : e3;

        cA = sigf(fA) * cA + sigf(iA) * tanh_(gA);
        float hA = sigf(oA) * tanh_(cA);
        shf[nxt * 512 + mA * 128 + u] = hA;
        if (t < lenA) hsA[(size_t)t * HH] = hA;

        cB = sigf(fB) * cB + sigf(iB) * tanh_(gB);
        float hB = sigf(oB) * tanh_(cB);
        shf[nxt * 512 + mB * 128 + u] = hB;
        if (t < lenB) hsB[(size_t)t * HH] = hB;

        __syncthreads();
    }

    // zero masked tails so the feats GEMM can ignore lengths
    for (int t = lenA; t < TT; t++) hsA[(size_t)t * HH] = 0.0f;
    for (int t = lenB; t < TT; t++) hsB[(size_t)t * HH] = 0.0f;
}

// ---------------- kernel 6: feats GEMM (split-K, tiled, f32x2) -------------------
// psum[kz][n][j] = sum_{t in chunk} sum_h hs[n][t][h] * W1[j][t*128+h]
__global__ void __launch_bounds__(256) k_feats(const float* __restrict__ W1) {
    __shared__ __align__(16) float sh_hs[TM][HH + 4];     // padded: conflict-free
    __shared__ __align__(16) float sh_w[NINTER][HH];

    int tile = blockIdx.x;        // 0..39
    int kz = blockIdx.y;          // 0..7
    int tid = threadIdx.x;
    int s0 = tid & 15;            // rows s0 and s0+16
    int j0 = (tid >> 4) * 4;      // 4 inter cols
    u64 a0[4] = {0, 0, 0, 0};
    u64 a1[4] = {0, 0, 0, 0};

    int t0 = kz * TCHUNK;
    for (int tt = 0; tt < TCHUNK; tt++) {
        int t = t0 + tt;
        __syncthreads();
        for (int i = tid; i < TM * 32; i += 256) {
            int s = i >> 5, kq = i & 31;
            ((float4*)&sh_hs[s][0])[kq] =
                ((const float4*)(g_hs + ((size_t)(tile * TM + s) * TT + t) * HH))[kq];
        }
        for (int i = tid; i < NINTER * 32; i += 256) {
            int j = i >> 5, kq = i & 31;
            ((float4*)&sh_w[j][0])[kq] =
                ((const float4*)(W1 + (size_t)j * (TT * HH) + (size_t)t * HH))[kq];
        }
        __syncthreads();
        #pragma unroll 4
        for (int kq = 0; kq < 32; kq++) {
            ulonglong2 hA = ((const ulonglong2*)&sh_hs[s0][0])[kq];
            ulonglong2 hB = ((const ulonglong2*)&sh_hs[s0 + 16][0])[kq];
            #pragma unroll
            for (int c = 0; c < 4; c++) {
                ulonglong2 w = ((const ulonglong2*)&sh_w[j0 + c][0])[kq];
                a0[c] = ffma2(hA.x, w.x, a0[c]); a0[c] = ffma2(hA.y, w.y, a0[c]);
                a1[c] = ffma2(hB.x, w.x, a1[c]); a1[c] = ffma2(hB.y, w.y, a1[c]);
            }
        }
    }
    int srow = tile * TM;
    size_t baseA = ((size_t)kz * NN + (srow + s0)) * NINTER + j0;
    size_t baseB = ((size_t)kz * NN + (srow + s0 + 16)) * NINTER + j0;
    #pragma unroll
    for (int c = 0; c < 4; c++) {
        g_psum[baseA + c] = f2lo(a0[c]) + f2hi(a0[c]);
        g_psum[baseB + c] = f2lo(a1[c]) + f2hi(a1[c]);
    }
}

// ---------------- kernel 7: reduce split-K + bias + final linear -----------------
__global__ void __launch_bounds__(256) k_final(
    const float* __restrict__ b1, const float* __restrict__ W2,
    const float* __restrict__ b2, float* __restrict__ out)
{
    __shared__ float sf[SS * NINTER];   // 1280 feats for this batch
    __shared__ float r0[256], r1[256];
    int b = blockIdx.x, tid = threadIdx.x;

    for (int i = tid; i < SS * NINTER; i += 256) {
        int s = i / NINTER, j = i % NINTER;
        size_t nq = (size_t)b * SS + s;
        float v = b1[j];
        #pragma unroll
        for (int kz = 0; kz < KSPLIT; kz++)
            v += g_psum[((size_t)kz * NN + nq) * NINTER + j];
        sf[i] = v;
    }
    __syncthreads();
    float p0 = 0.f, p1 = 0.f;
    for (int i = tid; i < SS * NINTER; i += 256) {
        float f = sf[i];
        p0 += f * W2[i];
        p1 += f * W2[SS * NINTER + i];
    }
    r0[tid] = p0; r1[tid] = p1;
    __syncthreads();
    for (int off = 128; off; off >>= 1) {
        if (tid < off) { r0[tid] += r0[tid + off]; r1[tid] += r1[tid + off]; }
        __syncthreads();
    }
    if (tid == 0) {
        out[b * 2 + 0] = r0[0] + b2[0];
        out[b * 2 + 1] = r1[0] + b2[1];
    }
}

// ---------------- launch ----------------------------------------------------------
extern "C" void kernel_launch(void* const* d_in, const int* in_sizes, int n_in,
                              void* d_out, int out_size)
{
    const float* x   = (const float*)d_in[0];
    // d_in[1] = metadata (unused by the reference computation)
    const float* Wih = (const float*)d_in[2];
    const float* Whh = (const float*)d_in[3];
    const float* bih = (const float*)d_in[4];
    const float* bhh = (const float*)d_in[5];
    const float* W1  = (const float*)d_in[6];
    const float* b1  = (const float*)d_in[7];
    const float* W2  = (const float*)d_in[8];
    const float* b2  = (const float*)d_in[9];
    float* out = (float*)d_out;

    cudaFuncSetAttribute(k_lstm, cudaFuncAttributeMaxDynamicSharedMemorySize, LSTM_SMEM);

    k_zero_hist<<<1, 256>>>();
    k_lens<<<NN, 32>>>(x);
    k_prefix<<<1, 32>>>();
    k_scatter<<<5, 256>>>();
    k_wt<<<64, 256>>>(Whh);
    k_lstm<<<NG, 256, LSTM_SMEM>>>(x, Wih, bih, bhh);
    k_feats<<<dim3(40, KSPLIT), 256>>>(W1);
    k_final<<<BB, 256>>>(b1, W2, b2, out);
}